// round 3
// baseline (speedup 1.0000x reference)
#include <cuda_runtime.h>
#include <cstdint>

#define N_IN    16
#define N_MF    2
#define N_RULES 64
#define NPAIR   32        // rule pairs processed per loop iteration
#define TPB     64
#define RPT     2         // rows per thread, packed into f32x2 lanes

typedef unsigned long long ull;

// ---------- f32x2 helpers (sm_100a packed fp32) ----------
__device__ __forceinline__ ull pack2(float lo, float hi) {
    ull r;
    asm("mov.b64 %0, {%1, %2};" : "=l"(r) : "f"(lo), "f"(hi));
    return r;
}
__device__ __forceinline__ void unpack2(ull v, float& lo, float& hi) {
    asm("mov.b64 {%0, %1}, %2;" : "=f"(lo), "=f"(hi) : "l"(v));
}
__device__ __forceinline__ ull ffma2(ull a, ull b, ull c) {
    ull d;
    asm("fma.rn.f32x2 %0, %1, %2, %3;" : "=l"(d) : "l"(a), "l"(b), "l"(c));
    return d;
}
__device__ __forceinline__ ull fadd2(ull a, ull b) {
    ull d;
    asm("add.rn.f32x2 %0, %1, %2;" : "=l"(d) : "l"(a), "l"(b));
    return d;
}
__device__ __forceinline__ ull fmul2(ull a, ull b) {
    ull d;
    asm("mul.rn.f32x2 %0, %1, %2;" : "=l"(d) : "l"(a), "l"(b));
    return d;
}
__device__ __forceinline__ float ex2_fast(float x) {
    float y;
    asm("ex2.approx.f32 %0, %1;" : "=f"(y) : "f"(x));
    return y;
}

// -0.5 * log2(e), 1/ln(2)
#define NEG_HALF_LOG2E (-0.7213475204444817f)
#define LOG2E          ( 1.4426950408889634f)

// ---------- constant blob: all warp-uniform operands, pre-duplicated ----------
struct Blob {
    float4 mask4[NPAIR][N_IN];      // (m_e, m_e, m_o, m_o)
    float4 cons4[NPAIR][N_IN + 1];  // (c_e, c_e, c_o, c_o); [16] = bias
    float4 am4[NPAIR];              // (a_e, a_e, a_o, a_o)
    float2 vfb2[N_IN + 1];          // fallback vector, duplicated (v, v)
    float2 cen[N_IN];               // (c0, c1)
    float2 inv[N_IN];               // 1/(exp(log_sigma)+1e-6)
};

__constant__ Blob c_blob;
__device__   Blob g_stage;

// ---------- prep kernel: build the blob in the staging buffer ----------
__global__ void prep_kernel(const float* __restrict__ center,
                            const float* __restrict__ log_sigma,
                            const float* __restrict__ consequent,
                            const int*   __restrict__ rule_idx,
                            const float* __restrict__ amask)
{
    const int tid = threadIdx.x;

    for (int idx = tid; idx < NPAIR * N_IN; idx += blockDim.x) {
        int p = idx >> 4, i = idx & 15;
        float m0 = (float)rule_idx[(2 * p)     * N_IN + i];
        float m1 = (float)rule_idx[(2 * p + 1) * N_IN + i];
        g_stage.mask4[p][i] = make_float4(m0, m0, m1, m1);
    }
    for (int idx = tid; idx < NPAIR * (N_IN + 1); idx += blockDim.x) {
        int p = idx / (N_IN + 1), i = idx % (N_IN + 1);
        float c0 = consequent[(2 * p)     * (N_IN + 1) + i];
        float c1 = consequent[(2 * p + 1) * (N_IN + 1) + i];
        g_stage.cons4[p][i] = make_float4(c0, c0, c1, c1);
    }
    if (tid < NPAIR) {
        float a0 = amask[2 * tid], a1 = amask[2 * tid + 1];
        g_stage.am4[tid] = make_float4(a0, a0, a1, a1);
    }
    if (tid < N_IN + 1) {
        float asum = 0.f;
        for (int r = 0; r < N_RULES; r++) asum += amask[r];
        float s = 1.0f / fmaxf(asum, 1.0f);
        float v = 0.f;
        for (int r = 0; r < N_RULES; r++)
            v += amask[r] * consequent[r * (N_IN + 1) + tid];
        v *= s;
        g_stage.vfb2[tid] = make_float2(v, v);
    }
    if (tid < N_IN) {
        g_stage.cen[tid] = make_float2(center[tid * N_MF + 0],
                                       center[tid * N_MF + 1]);
        g_stage.inv[tid] = make_float2(
            1.0f / (expf(log_sigma[tid * N_MF + 0]) + 1e-6f),
            1.0f / (expf(log_sigma[tid * N_MF + 1]) + 1e-6f));
    }
}

// ---------- main kernel: no shared memory; uniform operands via const path ----
__global__ __launch_bounds__(TPB)
void anfis_kernel(const float* __restrict__ x,   // [B,16]
                  float* __restrict__ out, int B)
{
    const int tid = threadIdx.x;
    const int rowA = blockIdx.x * (TPB * RPT) + tid;
    if (rowA >= B) return;
    int rowB = rowA + TPB;
    const bool hasB = (rowB < B);
    if (!hasB) rowB = rowA;

    // ---- load both rows (float4 vectorized, coalesced) ----
    const float4* xva = reinterpret_cast<const float4*>(x + (size_t)rowA * N_IN);
    const float4* xvb = reinterpret_cast<const float4*>(x + (size_t)rowB * N_IN);
    float4 a0 = xva[0], a1 = xva[1], a2 = xva[2], a3 = xva[3];
    float4 b0 = xvb[0], b1 = xvb[1], b2 = xvb[2], b3 = xvb[3];
    float xA[N_IN] = {a0.x, a0.y, a0.z, a0.w, a1.x, a1.y, a1.z, a1.w,
                      a2.x, a2.y, a2.z, a2.w, a3.x, a3.y, a3.z, a3.w};
    float xB[N_IN] = {b0.x, b0.y, b0.z, b0.w, b1.x, b1.y, b1.z, b1.w,
                      b2.x, b2.y, b2.z, b2.w, b3.x, b3.y, b3.z, b3.w};

    // ---- membership in log2 space; lanes = (rowA, rowB) ----
    float baseA = 0.f, baseB = 0.f;
    ull diffAB[N_IN], xAB[N_IN];
    #pragma unroll
    for (int i = 0; i < N_IN; i++) {
        float2 cen = c_blob.cen[i];
        float2 inv = c_blob.inv[i];
        float dA0 = (xA[i] - cen.x) * inv.x, dA1 = (xA[i] - cen.y) * inv.y;
        float dB0 = (xB[i] - cen.x) * inv.x, dB1 = (xB[i] - cen.y) * inv.y;
        float lA0 = dA0 * dA0 * NEG_HALF_LOG2E;
        float lA1 = dA1 * dA1 * NEG_HALF_LOG2E;
        float lB0 = dB0 * dB0 * NEG_HALF_LOG2E;
        float lB1 = dB1 * dB1 * NEG_HALF_LOG2E;
        baseA += lA0;
        baseB += lB0;
        diffAB[i] = pack2(lA1 - lA0, lB1 - lB0);
        xAB[i]    = pack2(xA[i], xB[i]);
    }
    const ull base2 = pack2(baseA, baseB);

    ull fs2  = 0ull;   // (fsA, fsB)
    ull acc2 = 0ull;   // (accA, accB)

    #pragma unroll 4
    for (int p = 0; p < NPAIR; p++) {
        // even/odd rule of the pair, rows packed in lanes
        ull tE = base2, tO = base2;
        const ulonglong2 cb =
            *reinterpret_cast<const ulonglong2*>(&c_blob.cons4[p][N_IN]);
        ull roE = cb.x, roO = cb.y;

        #pragma unroll
        for (int i = 0; i < N_IN; i++) {
            ulonglong2 m =
                *reinterpret_cast<const ulonglong2*>(&c_blob.mask4[p][i]);
            tE = ffma2(diffAB[i], m.x, tE);
            tO = ffma2(diffAB[i], m.y, tO);
            ulonglong2 c =
                *reinterpret_cast<const ulonglong2*>(&c_blob.cons4[p][i]);
            roE = ffma2(xAB[i], c.x, roE);
            roO = ffma2(xAB[i], c.y, roO);
        }

        float tEa, tEb, tOa, tOb;
        unpack2(tE, tEa, tEb);
        unpack2(tO, tOa, tOb);
        ull fE = pack2(ex2_fast(tEa), ex2_fast(tEb));
        ull fO = pack2(ex2_fast(tOa), ex2_fast(tOb));

        ulonglong2 am = *reinterpret_cast<const ulonglong2*>(&c_blob.am4[p]);
        fE = fmul2(fE, am.x);
        fO = fmul2(fO, am.y);

        fs2  = fadd2(fs2, fadd2(fE, fO));
        acc2 = ffma2(fE, roE, acc2);
        acc2 = ffma2(fO, roO, acc2);
    }

    // fallback: v_fb . x_aug (row-independent vector, 17 packed FMAs)
    ull fb2 = *reinterpret_cast<const ull*>(&c_blob.vfb2[N_IN]);  // bias
    #pragma unroll
    for (int i = 0; i < N_IN; i++)
        fb2 = ffma2(xAB[i], *reinterpret_cast<const ull*>(&c_blob.vfb2[i]), fb2);

    float fsA, fsB, accA, accB, fbA, fbB;
    unpack2(fs2, fsA, fsB);
    unpack2(acc2, accA, accB);
    unpack2(fb2, fbA, fbB);

    float zA = (fsA <= 1e-12f) ? fbA : __fdividef(accA, fsA);
    float zB = (fsB <= 1e-12f) ? fbB : __fdividef(accB, fsB);

    float sA = __fdividef(1.0f, 1.0f + ex2_fast(-zA * LOG2E));
    float sB = __fdividef(1.0f, 1.0f + ex2_fast(-zB * LOG2E));
    sA = fminf(fmaxf(sA, 1e-7f), 1.0f - 1e-7f);
    sB = fminf(fmaxf(sB, 1e-7f), 1.0f - 1e-7f);

    out[rowA] = sA;
    if (hasB) out[rowA + TPB] = sB;
}

extern "C" void kernel_launch(void* const* d_in, const int* in_sizes, int n_in,
                              void* d_out, int out_size)
{
    const float* x          = (const float*)d_in[0];
    const float* center     = (const float*)d_in[1];
    const float* log_sigma  = (const float*)d_in[2];
    const float* consequent = (const float*)d_in[3];
    const int*   rule_idx   = (const int*)  d_in[4];
    const float* amask      = (const float*)d_in[5];
    float*       out        = (float*)d_out;

    int B = in_sizes[0] / N_IN;

    // 1) build uniform-operand blob in device staging
    prep_kernel<<<1, 128>>>(center, log_sigma, consequent, rule_idx, amask);

    // 2) copy staging -> __constant__ (D2D async memcpy: graph-capturable)
    void* src = nullptr;
    cudaGetSymbolAddress(&src, g_stage);
    cudaMemcpyToSymbolAsync(c_blob, src, sizeof(Blob), 0,
                            cudaMemcpyDeviceToDevice, 0);

    // 3) main kernel
    int rows_per_block = TPB * RPT;
    int grid = (B + rows_per_block - 1) / rows_per_block;
    anfis_kernel<<<grid, TPB>>>(x, out, B);
}